// round 14
// baseline (speedup 1.0000x reference)
#include <cuda_runtime.h>
#include <cstddef>
#include <cstdint>

#define NN 20000
#define EE 320000
#define HH 128
#define KK 4
#define BB 64
#define CAP 64

#define OFF_LOGITS 0
#define OFF_HSTAB  512
#define OFF_HORIG  33280
#define OFF_NM     41472
#define OFF_EM     121472

#define NH4 ((size_t)NN * HH * 4)
// As[64][132] + 2 x Wq[32][132]  = 128*132*4 = 67584 B  -> 3 blocks/SM
#define SMEM_BYTES (128 * 132 * 4)

// scratch layout
#define SC_Z       0
#define SC_DEG     (SC_Z + NH4)
#define SC_ADJSRC  (SC_DEG + (size_t)NN * 4)
#define SC_ADJEID  (SC_ADJSRC + (size_t)NN * CAP * 4)
#define SC_CNT     (SC_ADJEID + (size_t)NN * CAP * 4)
#define SC_BSTART  (SC_CNT + (size_t)BB * 4)
#define SC_EXP     (SC_BSTART + 384)
#define EXP_STRIDE_F (3 * (size_t)NN * HH + (size_t)EE)
#define SC_TOTAL   (SC_EXP + 4 * EXP_STRIDE_F * 4)

__device__ __align__(128) unsigned char g_scratch[SC_TOTAL];

// ---------------- helpers ----------------
__device__ __forceinline__ void ffma2(unsigned long long& d, unsigned long long a, unsigned long long b) {
    asm("fma.rn.f32x2 %0, %1, %2, %0;" : "+l"(d) : "l"(a), "l"(b));
}
__device__ __forceinline__ unsigned long long dup2(float x) {
    unsigned long long r;
    asm("mov.b64 %0, {%1, %1};" : "=l"(r) : "f"(x));
    return r;
}
__device__ __forceinline__ void unpack2(unsigned long long v, float& lo, float& hi) {
    asm("mov.b64 {%0, %1}, %2;" : "=f"(lo), "=f"(hi) : "l"(v));
}
__device__ __forceinline__ float* arena(int k) {
    return (float*)(g_scratch + SC_EXP) + (size_t)k * EXP_STRIDE_F;
}
__device__ __forceinline__ void cp16(void* smem_dst, const void* gmem_src) {
    uint32_t s = (uint32_t)__cvta_generic_to_shared(smem_dst);
    asm volatile("cp.async.cg.shared.global [%0], [%1], 16;" :: "r"(s), "l"(gmem_src));
}
#define CP_COMMIT() asm volatile("cp.async.commit_group;" ::: "memory")
#define CP_WAIT0()  asm volatile("cp.async.wait_group 0;" ::: "memory")

// load one 32-row W quarter (32x128 floats) into a quarter buffer (stride 132)
__device__ __forceinline__ void load_wq(float* buf, const float* Wsrc, int tid) {
#pragma unroll
    for (int c = tid; c < 1024; c += 256) {       // 1024 chunks of 16B
        int r = c >> 5;
        int col = c & 31;
        cp16(buf + r * 132 + col * 4, Wsrc + (size_t)r * HH + col * 4);
    }
}

// ---------------- setup ----------------
__global__ void k_zero_all(int* deg, float* nm) {
    int i = blockIdx.x * blockDim.x + threadIdx.x;
    if (i < NN) deg[i] = 0;
    if (i < NN * KK) nm[i] = 0.f;
}

__global__ void k_build_adj(const int* __restrict__ src, const int* __restrict__ dst,
                            int* deg, int* adj_src, int* adj_eid) {
    int e = blockIdx.x * blockDim.x + threadIdx.x;
    if (e >= EE) return;
    int d = dst[e];
    int slot = atomicAdd(&deg[d], 1);
    if (slot < CAP) {
        adj_src[d * CAP + slot] = src[e];
        adj_eid[d * CAP + slot] = e;
    }
}

__global__ void k_sort_adj(const int* __restrict__ deg, int* adj_src, int* adj_eid) {
    int n = blockIdx.x * blockDim.x + threadIdx.x;
    if (n >= NN) return;
    int d = deg[n]; if (d > CAP) d = CAP;
    int* es = adj_eid + n * CAP;
    int* ss = adj_src + n * CAP;
    for (int i = 1; i < d; i++) {
        int ke = es[i], ks = ss[i];
        int j = i - 1;
        while (j >= 0 && es[j] > ke) { es[j + 1] = es[j]; ss[j + 1] = ss[j]; j--; }
        es[j + 1] = ke; ss[j + 1] = ks;
    }
}

// batch is sorted: cnt/bstart via binary search
__global__ void k_bounds(const int* __restrict__ batch, int* cnt, int* bstart) {
    int g = threadIdx.x;
    if (g >= BB) return;
    int lo = 0, hi = NN;
    while (lo < hi) { int mid = (lo + hi) >> 1; if (batch[mid] < g) lo = mid + 1; else hi = mid; }
    int lo2 = lo, hi2 = NN;
    while (lo2 < hi2) { int mid = (lo2 + hi2) >> 1; if (batch[mid] < g + 1) lo2 = mid + 1; else hi2 = mid; }
    bstart[g] = lo;
    cnt[g] = lo2 - lo;
}

// ---------------- aggregation (gather, deterministic, high occupancy) ----------------
__global__ void k_agg_enc(const float* __restrict__ h, float* __restrict__ agg,
                          const int* __restrict__ deg, const int* __restrict__ adj_src) {
    int node = blockIdx.x * (blockDim.x >> 5) + (threadIdx.x >> 5);
    if (node >= NN) return;
    int lane = threadIdx.x & 31;
    int d = deg[node]; if (d > CAP) d = CAP;
    const int* ss = adj_src + node * CAP;
    float4 acc = make_float4(0.f, 0.f, 0.f, 0.f);
    for (int i = 0; i < d; i++) {
        float4 v = *(const float4*)(h + (size_t)ss[i] * HH + (lane << 2));
        acc.x += v.x; acc.y += v.y; acc.z += v.z; acc.w += v.w;
    }
    *(float4*)(agg + (size_t)node * HH + (lane << 2)) = acc;
}

template <bool MASKX>
__global__ void k_agg_cls(const float* __restrict__ x, const float* __restrict__ nm,
                          const int* __restrict__ deg, const int* __restrict__ adj_src,
                          const int* __restrict__ adj_eid) {
    int node = blockIdx.x * (blockDim.x >> 5) + (threadIdx.x >> 5);
    if (node >= NN) return;
    int k = blockIdx.y;
    float* a = arena(k);
    const float* h = MASKX ? x : a;
    float* agg = a + 2 * (size_t)NN * HH;
    const float* eon = a + 3 * (size_t)NN * HH;
    int lane = threadIdx.x & 31;
    int d = deg[node]; if (d > CAP) d = CAP;
    const int* ss = adj_src + node * CAP;
    const int* es = adj_eid + node * CAP;
    float4 acc = make_float4(0.f, 0.f, 0.f, 0.f);
    for (int i = 0; i < d; i++) {
        float w = eon[es[i]];
        if (w == 0.f) continue;
        int s = ss[i];
        float4 v = *(const float4*)(h + (size_t)s * HH + (lane << 2));
        if (MASKX) {
            float m = nm[(size_t)s * KK + k];
            v.x *= m; v.y *= m; v.z *= m; v.w *= m;
        }
        acc.x += w * v.x; acc.y += w * v.y; acc.z += w * v.z; acc.w += w * v.w;
    }
    *(float4*)(agg + (size_t)node * HH + (lane << 2)) = acc;
}

// ---------------- pipelined 64x128x128 GEMM core (broadcast-B thread mapping) ----------------
// Thread mapping: warp w owns cols [w*16, w*16+16); within warp, c0 = w*16 + (lane>>3)*4,
// rows = (lane&7) + 8*i for i in 0..7. B-LDS is 8-way broadcast (64B distinct -> 1 cyc);
// A-LDS hits 8 distinct conflict-free banks (1 cyc). k-accumulation order 0..127 unchanged.
__device__ __forceinline__ void gemm_quarters(const float* As, float* Wb0, float* Wb1,
                                              const float* __restrict__ W, int tid,
                                              int rlane, int c0, unsigned long long acc[8][2]) {
    load_wq(Wb0, W, tid);
    CP_COMMIT(); CP_WAIT0();
    __syncthreads();
#pragma unroll 1
    for (int q = 0; q < 4; q++) {
        float* cur = (q & 1) ? Wb1 : Wb0;
        if (q < 3) { load_wq((q & 1) ? Wb0 : Wb1, W + (size_t)(q + 1) * 32 * HH, tid); CP_COMMIT(); }
        const float* arow = As + rlane * 132 + q * 32;
#pragma unroll 2
        for (int k = 0; k < 32; k += 4) {
            ulonglong2 b0 = *(const ulonglong2*)(cur + (k + 0) * 132 + c0);
            ulonglong2 b1v = *(const ulonglong2*)(cur + (k + 1) * 132 + c0);
            ulonglong2 b2v = *(const ulonglong2*)(cur + (k + 2) * 132 + c0);
            ulonglong2 b3v = *(const ulonglong2*)(cur + (k + 3) * 132 + c0);
#pragma unroll
            for (int i = 0; i < 8; i++) {
                float4 a4 = *(const float4*)(arow + i * 8 * 132 + k);
                unsigned long long ax = dup2(a4.x), ay = dup2(a4.y);
                unsigned long long az = dup2(a4.z), aw = dup2(a4.w);
                ffma2(acc[i][0], ax, b0.x);  ffma2(acc[i][1], ax, b0.y);
                ffma2(acc[i][0], ay, b1v.x); ffma2(acc[i][1], ay, b1v.y);
                ffma2(acc[i][0], az, b2v.x); ffma2(acc[i][1], az, b2v.y);
                ffma2(acc[i][0], aw, b3v.x); ffma2(acc[i][1], aw, b3v.y);
            }
        }
        if (q < 3) CP_WAIT0();
        __syncthreads();
    }
}

// ---------------- fused MLP (agg-in epilogue, 2 GEMMs, pipelined W) ----------------
template <bool MASKX>
__device__ __forceinline__ void mlp_body(float* sm,
    const float* __restrict__ X, const float* __restrict__ nm, int kidx,
    const float* __restrict__ AGG, const float* __restrict__ epsp,
    const float* __restrict__ W1, const float* __restrict__ b1,
    const float* __restrict__ W2, const float* __restrict__ b2,
    float* __restrict__ out, int row0)
{
    float* As  = sm;               // [64][132]
    float* Wb0 = sm + 64 * 132;    // [32][132]
    float* Wb1 = Wb0 + 32 * 132;   // [32][132]
    int tid = threadIdx.x;
    float ep = 1.f + *epsp;

    for (int i = tid; i < 64 * 32; i += 256) {
        int r = i >> 5;
        int cc = (i & 31) << 2;
        int gr = row0 + r;
        float4 v = make_float4(0.f, 0.f, 0.f, 0.f);
        if (gr < NN) {
            v = *(const float4*)(X + (size_t)gr * HH + cc);
            if (MASKX) {
                float m = nm[(size_t)gr * KK + kidx];
                v.x *= m; v.y *= m; v.z *= m; v.w *= m;
            }
            float4 a = *(const float4*)(AGG + (size_t)gr * HH + cc);
            v.x = __fmaf_rn(ep, v.x, a.x); v.y = __fmaf_rn(ep, v.y, a.y);
            v.z = __fmaf_rn(ep, v.z, a.z); v.w = __fmaf_rn(ep, v.w, a.w);
        }
        *(float4*)&As[r * 132 + cc] = v;
    }
    // As is made visible by the sync inside gemm_quarters (after W q0 load).

    int lane = tid & 31;
    int rlane = lane & 7;                          // base row class
    int c0 = (tid >> 5) * 16 + ((lane >> 3) << 2); // warp-owned 16-col strip
    unsigned long long acc[8][2];

    // ---- GEMM 1 ----
#pragma unroll
    for (int i = 0; i < 8; i++) { acc[i][0] = 0ull; acc[i][1] = 0ull; }
    gemm_quarters(As, Wb0, Wb1, W1, tid, rlane, c0, acc);

    // mid -> As (each element written exactly once; full barrier before GEMM2 is
    // the sync inside gemm_quarters after W2-q0 load)
    {
        float4 bv = *(const float4*)(b1 + c0);
#pragma unroll
        for (int i = 0; i < 8; i++) {
            float x0, x1, x2, x3;
            unpack2(acc[i][0], x0, x1);
            unpack2(acc[i][1], x2, x3);
            x0 += bv.x; x1 += bv.y; x2 += bv.z; x3 += bv.w;
            x0 = fmaxf(x0, 0.f); x1 = fmaxf(x1, 0.f);
            x2 = fmaxf(x2, 0.f); x3 = fmaxf(x3, 0.f);
            *(float4*)&As[(rlane + 8 * i) * 132 + c0] = make_float4(x0, x1, x2, x3);
        }
    }

    // ---- GEMM 2 ----
#pragma unroll
    for (int i = 0; i < 8; i++) { acc[i][0] = 0ull; acc[i][1] = 0ull; }
    gemm_quarters(As, Wb0, Wb1, W2, tid, rlane, c0, acc);

    {
        float4 bv = *(const float4*)(b2 + c0);
#pragma unroll
        for (int i = 0; i < 8; i++) {
            int gr = row0 + rlane + 8 * i;
            if (gr < NN) {
                float x0, x1, x2, x3;
                unpack2(acc[i][0], x0, x1);
                unpack2(acc[i][1], x2, x3);
                x0 += bv.x; x1 += bv.y; x2 += bv.z; x3 += bv.w;
                x0 = fmaxf(x0, 0.f); x1 = fmaxf(x1, 0.f);
                x2 = fmaxf(x2, 0.f); x3 = fmaxf(x3, 0.f);
                *(float4*)(out + (size_t)gr * HH + c0) = make_float4(x0, x1, x2, x3);
            }
        }
    }
}

__global__ void __launch_bounds__(256, 3)
k_mlp_enc(const float* __restrict__ X, const float* __restrict__ AGG,
          const float* __restrict__ epsp,
          const float* __restrict__ W1, const float* __restrict__ b1,
          const float* __restrict__ W2, const float* __restrict__ b2,
          float* __restrict__ out) {
    extern __shared__ float sm[];
    mlp_body<false>(sm, X, nullptr, 0, AGG, epsp, W1, b1, W2, b2, out, blockIdx.x * 64);
}

__global__ void __launch_bounds__(256, 3)
k_mlp_cls(int l, const float* __restrict__ x, const float* __restrict__ nm,
          const float* __restrict__ cls_eps,
          const float* __restrict__ cls_W1, const float* __restrict__ cls_b1,
          const float* __restrict__ cls_W2, const float* __restrict__ cls_b2) {
    extern __shared__ float sm[];
    int k = blockIdx.y;
    int wl = k * 3 + l;
    float* a = arena(k);
    if (l == 0) {
        mlp_body<true>(sm, x, nm, k, a + 2 * (size_t)NN * HH, cls_eps + wl,
                       cls_W1 + (size_t)wl * HH * HH, cls_b1 + wl * HH,
                       cls_W2 + (size_t)wl * HH * HH, cls_b2 + wl * HH,
                       a, blockIdx.x * 64);
    } else {
        mlp_body<false>(sm, a, nullptr, 0, a + 2 * (size_t)NN * HH, cls_eps + wl,
                        cls_W1 + (size_t)wl * HH * HH, cls_b1 + wl * HH,
                        cls_W2 + (size_t)wl * HH * HH, cls_b2 + wl * HH,
                        a, blockIdx.x * 64);
    }
}

// ---------------- mask projection GEMM, batched grid (GB, 2, K), pipelined W ----------------
__global__ void __launch_bounds__(256, 3)
k_gemm_mask(const float* __restrict__ Z, const float* __restrict__ mask_W1) {
    extern __shared__ float sm[];
    float* As  = sm;
    float* Wb0 = sm + 64 * 132;
    float* Wb1 = Wb0 + 32 * 132;
    int tid = threadIdx.x;
    int row0 = blockIdx.x * 64;
    int k = blockIdx.z;
    const float* W = mask_W1 + ((size_t)k * 2 + blockIdx.y) * HH * HH;
    float* out = arena(k) + (1 + blockIdx.y) * (size_t)NN * HH;

    for (int i = tid; i < 64 * 32; i += 256) {
        int r = i >> 5;
        int cc = (i & 31) << 2;
        int gr = row0 + r;
        float4 v = make_float4(0.f, 0.f, 0.f, 0.f);
        if (gr < NN) v = *(const float4*)(Z + (size_t)gr * HH + cc);
        *(float4*)&As[r * 132 + cc] = v;
    }

    int lane = tid & 31;
    int rlane = lane & 7;
    int c0 = (tid >> 5) * 16 + ((lane >> 3) << 2);
    unsigned long long acc[8][2];
#pragma unroll
    for (int i = 0; i < 8; i++) { acc[i][0] = 0ull; acc[i][1] = 0ull; }
    gemm_quarters(As, Wb0, Wb1, W, tid, rlane, c0, acc);

#pragma unroll
    for (int i = 0; i < 8; i++) {
        int gr = row0 + rlane + 8 * i;
        if (gr < NN) {
            float x0, x1, x2, x3;
            unpack2(acc[i][0], x0, x1);
            unpack2(acc[i][1], x2, x3);
            *(float4*)(out + (size_t)gr * HH + c0) = make_float4(x0, x1, x2, x3);
        }
    }
}

// ---------------- edge mask (warp per edge, batched over experts) ----------------
__global__ void k_edgemask(const int* __restrict__ src, const int* __restrict__ dst,
                           const float* __restrict__ u, const float* __restrict__ mask_b1,
                           const float* __restrict__ mask_w2, const float* __restrict__ mask_b2,
                           float* __restrict__ nm, float* __restrict__ em) {
    int e = blockIdx.x * (blockDim.x >> 5) + (threadIdx.x >> 5);
    if (e >= EE) return;
    int kk = blockIdx.y;
    float* a4 = arena(kk);
    const float* Abuf = a4 + (size_t)NN * HH;
    const float* Bbuf = a4 + 2 * (size_t)NN * HH;
    float* eon = a4 + 3 * (size_t)NN * HH;
    const float* b1 = mask_b1 + kk * HH;
    const float* w2 = mask_w2 + kk * HH;

    int lane = threadIdx.x & 31;
    int s = src[e], d = dst[e];
    float4 a = *(const float4*)(Abuf + (size_t)s * HH + (lane << 2));
    float4 b = *(const float4*)(Bbuf + (size_t)d * HH + (lane << 2));
    float4 bb = *(const float4*)(b1 + (lane << 2));
    float4 wv = *(const float4*)(w2 + (lane << 2));
    float h0 = fmaxf(a.x + b.x + bb.x, 0.f);
    float h1 = fmaxf(a.y + b.y + bb.y, 0.f);
    float h2 = fmaxf(a.z + b.z + bb.z, 0.f);
    float h3 = fmaxf(a.w + b.w + bb.w, 0.f);
    float p = h0 * wv.x + h1 * wv.y + h2 * wv.z + h3 * wv.w;
#pragma unroll
    for (int off = 16; off; off >>= 1) p += __shfl_xor_sync(0xffffffffu, p, off);
    if (lane == 0) {
        float eml = p + mask_b2[kk];
        float uu = u[(size_t)e * KK + kk];
        float g = -logf(-logf(uu + 1e-20f) + 1e-20f);
        float t = (eml + g) / 0.1f;
        float ys = 1.f / (1.f + expf(-t));
        float hard = (ys > 0.5f) ? 1.f : 0.f;
        float eo = (hard + ys) - ys;
        eon[e] = eo;
        em[(size_t)e * KK + kk] = eo;
        if (eo > 0.f) {
            nm[(size_t)s * KK + kk] = 1.f;
            nm[(size_t)d * KK + kk] = 1.f;
        }
    }
}

// ---------------- fused pool + head (+ h_orig plane): grid (BB, KK+1), 128 threads ----------------
__global__ void k_poolhead(const float* __restrict__ Z,
                           const int* __restrict__ cnt, const int* __restrict__ bstart,
                           const float* __restrict__ head_W1, const float* __restrict__ head_b1,
                           const float* __restrict__ head_W2, const float* __restrict__ head_b2,
                           float* __restrict__ out_hstab, float* __restrict__ out_logits,
                           float* __restrict__ out_horig) {
    __shared__ float sh[128], T[128];
    int g = blockIdx.x, kk = blockIdx.y, c = threadIdx.x;
    const float* h = (kk == KK) ? Z : arena(kk);
    int n0 = bstart[g], n = cnt[g];
    float a0 = 0.f, a1 = 0.f, a2 = 0.f, a3 = 0.f;
    int i = 0;
    for (; i + 4 <= n; i += 4) {
        a0 += h[(size_t)(n0 + i + 0) * HH + c];
        a1 += h[(size_t)(n0 + i + 1) * HH + c];
        a2 += h[(size_t)(n0 + i + 2) * HH + c];
        a3 += h[(size_t)(n0 + i + 3) * HH + c];
    }
    float acc = (a0 + a1) + (a2 + a3);
    for (; i < n; i++) acc += h[(size_t)(n0 + i) * HH + c];
    float v = acc / fmaxf((float)n, 1.f);

    if (kk == KK) {
        out_horig[(size_t)g * HH + c] = v;
        return;
    }
    out_hstab[((size_t)g * KK + kk) * HH + c] = v;
    sh[c] = v;
    __syncthreads();

    const float* W1 = head_W1 + (size_t)kk * HH * HH;
    float t = head_b1[kk * HH + c];
#pragma unroll 8
    for (int j = 0; j < 128; j++) t += sh[j] * W1[j * HH + c];
    T[c] = fmaxf(t, 0.f);
    __syncthreads();
    if (c < 2) {
        const float* W2 = head_W2 + (size_t)kk * HH * 2;
        float s = head_b2[kk * 2 + c];
        for (int j = 0; j < 128; j++) s += T[j] * W2[j * 2 + c];
        out_logits[((size_t)g * KK + kk) * 2 + c] = s;
    }
}

// ---------------- launcher ----------------
extern "C" void kernel_launch(void* const* d_in, const int* in_sizes, int n_in,
                              void* d_out, int out_size) {
    const float* x       = (const float*)d_in[0];
    const int*   ei      = (const int*)d_in[1];
    const int*   src     = ei;
    const int*   dst     = ei + EE;
    const int*   batch   = (const int*)d_in[2];
    const float* u       = (const float*)d_in[3];
    const float* enc_W1  = (const float*)d_in[4];
    const float* enc_b1  = (const float*)d_in[5];
    const float* enc_W2  = (const float*)d_in[6];
    const float* enc_b2  = (const float*)d_in[7];
    const float* enc_eps = (const float*)d_in[8];
    const float* cls_W1  = (const float*)d_in[9];
    const float* cls_b1  = (const float*)d_in[10];
    const float* cls_W2  = (const float*)d_in[11];
    const float* cls_b2  = (const float*)d_in[12];
    const float* cls_eps = (const float*)d_in[13];
    const float* mask_W1 = (const float*)d_in[14];
    const float* mask_b1 = (const float*)d_in[15];
    const float* mask_W2 = (const float*)d_in[16];
    const float* mask_b2 = (const float*)d_in[17];
    const float* head_W1 = (const float*)d_in[18];
    const float* head_b1 = (const float*)d_in[19];
    const float* head_W2 = (const float*)d_in[20];
    const float* head_b2 = (const float*)d_in[21];
    float* out = (float*)d_out;

    unsigned char* base = nullptr;
    cudaGetSymbolAddress((void**)&base, g_scratch);
    float* p_Z      = (float*)(base + SC_Z);
    int*   p_deg    = (int*)(base + SC_DEG);
    int*   p_asrc   = (int*)(base + SC_ADJSRC);
    int*   p_aeid   = (int*)(base + SC_ADJEID);
    int*   p_cnt    = (int*)(base + SC_CNT);
    int*   p_bstart = (int*)(base + SC_BSTART);
    float* arena0   = (float*)(base + SC_EXP);

    cudaFuncSetAttribute(k_mlp_enc,   cudaFuncAttributeMaxDynamicSharedMemorySize, SMEM_BYTES);
    cudaFuncSetAttribute(k_mlp_cls,   cudaFuncAttributeMaxDynamicSharedMemorySize, SMEM_BYTES);
    cudaFuncSetAttribute(k_gemm_mask, cudaFuncAttributeMaxDynamicSharedMemorySize, SMEM_BYTES);

    const int GB = (NN + 63) / 64;
    const int AB = (NN + 7) / 8;
    const int EB = (EE + 7) / 8;

    float* t0    = arena0;                        // enc temp h
    float* t_agg = arena0 + 2 * (size_t)NN * HH;  // enc agg temp

    // graph setup
    k_zero_all<<<(NN * KK + 255) / 256, 256>>>(p_deg, out + OFF_NM);
    k_build_adj<<<(EE + 255) / 256, 256>>>(src, dst, p_deg, p_asrc, p_aeid);
    k_sort_adj<<<(NN + 255) / 256, 256>>>(p_deg, p_asrc, p_aeid);

    // enc l0
    k_agg_enc<<<AB, 256>>>(x, t_agg, p_deg, p_asrc);
    k_bounds<<<1, BB>>>(batch, p_cnt, p_bstart);
    k_mlp_enc<<<GB, 256, SMEM_BYTES>>>(x, t_agg, enc_eps + 0, enc_W1, enc_b1,
                                       enc_W2, enc_b2, t0);

    // enc l1 (in-place t0), l2 (-> p_Z)
    k_agg_enc<<<AB, 256>>>(t0, t_agg, p_deg, p_asrc);
    k_mlp_enc<<<GB, 256, SMEM_BYTES>>>(t0, t_agg, enc_eps + 1, enc_W1 + HH * HH, enc_b1 + HH,
                                       enc_W2 + HH * HH, enc_b2 + HH, t0);
    k_agg_enc<<<AB, 256>>>(t0, t_agg, p_deg, p_asrc);
    k_mlp_enc<<<GB, 256, SMEM_BYTES>>>(t0, t_agg, enc_eps + 2, enc_W1 + 2 * HH * HH,
                                       enc_b1 + 2 * HH, enc_W2 + 2 * HH * HH, enc_b2 + 2 * HH, p_Z);

    // mask phase (batched)
    k_gemm_mask<<<dim3(GB, 2, KK), 256, SMEM_BYTES>>>(p_Z, mask_W1);
    k_edgemask<<<dim3(EB, KK), 256>>>(src, dst, u, mask_b1, mask_W2, mask_b2,
                                      out + OFF_NM, out + OFF_EM);

    // cls layers (batched over experts)
    k_agg_cls<true><<<dim3(AB, KK), 256>>>(x, out + OFF_NM, p_deg, p_asrc, p_aeid);
    k_mlp_cls<<<dim3(GB, KK), 256, SMEM_BYTES>>>(0, x, out + OFF_NM, cls_eps,
                                                 cls_W1, cls_b1, cls_W2, cls_b2);
    for (int l = 1; l < 3; l++) {
        k_agg_cls<false><<<dim3(AB, KK), 256>>>(x, out + OFF_NM, p_deg, p_asrc, p_aeid);
        k_mlp_cls<<<dim3(GB, KK), 256, SMEM_BYTES>>>(l, x, out + OFF_NM, cls_eps,
                                                     cls_W1, cls_b1, cls_W2, cls_b2);
    }

    // pools + heads (+ h_orig as extra y-plane)
    k_poolhead<<<dim3(BB, KK + 1), 128>>>(p_Z, p_cnt, p_bstart,
                                          head_W1, head_b1, head_W2, head_b2,
                                          out + OFF_HSTAB, out + OFF_LOGITS, out + OFF_HORIG);
}

// round 15
// speedup vs baseline: 1.0704x; 1.0704x over previous
#include <cuda_runtime.h>
#include <cstddef>
#include <cstdint>

#define NN 20000
#define EE 320000
#define HH 128
#define KK 4
#define BB 64
#define CAP 64

#define OFF_LOGITS 0
#define OFF_HSTAB  512
#define OFF_HORIG  33280
#define OFF_NM     41472
#define OFF_EM     121472

#define NH4 ((size_t)NN * HH * 4)
// As[64][132] + 2 x Wq[32][132]  = 128*132*4 = 67584 B  -> 3 blocks/SM
#define SMEM_BYTES (128 * 132 * 4)

// scratch layout
#define SC_Z       0
#define SC_DEG     (SC_Z + NH4)
#define SC_ADJSRC  (SC_DEG + (size_t)NN * 4)
#define SC_ADJEID  (SC_ADJSRC + (size_t)NN * CAP * 4)
#define SC_CNT     (SC_ADJEID + (size_t)NN * CAP * 4)
#define SC_BSTART  (SC_CNT + (size_t)BB * 4)
#define SC_EXP     (SC_BSTART + 384)
#define EXP_STRIDE_F (3 * (size_t)NN * HH + (size_t)EE)
#define SC_TOTAL   (SC_EXP + 4 * EXP_STRIDE_F * 4)

__device__ __align__(128) unsigned char g_scratch[SC_TOTAL];

// ---------------- helpers ----------------
__device__ __forceinline__ void ffma2(unsigned long long& d, unsigned long long a, unsigned long long b) {
    asm("fma.rn.f32x2 %0, %1, %2, %0;" : "+l"(d) : "l"(a), "l"(b));
}
__device__ __forceinline__ unsigned long long dup2(float x) {
    unsigned long long r;
    asm("mov.b64 %0, {%1, %1};" : "=l"(r) : "f"(x));
    return r;
}
__device__ __forceinline__ void unpack2(unsigned long long v, float& lo, float& hi) {
    asm("mov.b64 {%0, %1}, %2;" : "=f"(lo), "=f"(hi) : "l"(v));
}
__device__ __forceinline__ float* arena(int k) {
    return (float*)(g_scratch + SC_EXP) + (size_t)k * EXP_STRIDE_F;
}
__device__ __forceinline__ void cp16(void* smem_dst, const void* gmem_src) {
    uint32_t s = (uint32_t)__cvta_generic_to_shared(smem_dst);
    asm volatile("cp.async.cg.shared.global [%0], [%1], 16;" :: "r"(s), "l"(gmem_src));
}
#define CP_COMMIT() asm volatile("cp.async.commit_group;" ::: "memory")
#define CP_WAIT0()  asm volatile("cp.async.wait_group 0;" ::: "memory")

// load one 32-row W quarter (32x128 floats) into a quarter buffer (stride 132)
__device__ __forceinline__ void load_wq(float* buf, const float* Wsrc, int tid) {
#pragma unroll
    for (int c = tid; c < 1024; c += 256) {
        int r = c >> 5;
        int col = c & 31;
        cp16(buf + r * 132 + col * 4, Wsrc + (size_t)r * HH + col * 4);
    }
}

// ---------------- setup ----------------
__global__ void k_zero_all(int* deg, float* nm) {
    int i = blockIdx.x * blockDim.x + threadIdx.x;
    if (i < NN) deg[i] = 0;
    if (i < NN * KK) nm[i] = 0.f;
}

__global__ void k_build_adj(const int* __restrict__ src, const int* __restrict__ dst,
                            int* deg, int* adj_src, int* adj_eid) {
    int e = blockIdx.x * blockDim.x + threadIdx.x;
    if (e >= EE) return;
    int d = dst[e];
    int slot = atomicAdd(&deg[d], 1);
    if (slot < CAP) {
        adj_src[d * CAP + slot] = src[e];
        adj_eid[d * CAP + slot] = e;
    }
}

__global__ void k_sort_adj(const int* __restrict__ deg, int* adj_src, int* adj_eid) {
    int n = blockIdx.x * blockDim.x + threadIdx.x;
    if (n >= NN) return;
    int d = deg[n]; if (d > CAP) d = CAP;
    int* es = adj_eid + n * CAP;
    int* ss = adj_src + n * CAP;
    for (int i = 1; i < d; i++) {
        int ke = es[i], ks = ss[i];
        int j = i - 1;
        while (j >= 0 && es[j] > ke) { es[j + 1] = es[j]; ss[j + 1] = ss[j]; j--; }
        es[j + 1] = ke; ss[j + 1] = ks;
    }
}

// batch is sorted: cnt/bstart via binary search
__global__ void k_bounds(const int* __restrict__ batch, int* cnt, int* bstart) {
    int g = threadIdx.x;
    if (g >= BB) return;
    int lo = 0, hi = NN;
    while (lo < hi) { int mid = (lo + hi) >> 1; if (batch[mid] < g) lo = mid + 1; else hi = mid; }
    int lo2 = lo, hi2 = NN;
    while (lo2 < hi2) { int mid = (lo2 + hi2) >> 1; if (batch[mid] < g + 1) lo2 = mid + 1; else hi2 = mid; }
    bstart[g] = lo;
    cnt[g] = lo2 - lo;
}

// ---------------- aggregation ----------------
__global__ void k_agg_enc(const float* __restrict__ h, float* __restrict__ agg,
                          const int* __restrict__ deg, const int* __restrict__ adj_src) {
    int node = blockIdx.x * (blockDim.x >> 5) + (threadIdx.x >> 5);
    if (node >= NN) return;
    int lane = threadIdx.x & 31;
    int d = deg[node]; if (d > CAP) d = CAP;
    const int* ss = adj_src + node * CAP;
    float4 acc = make_float4(0.f, 0.f, 0.f, 0.f);
    for (int i = 0; i < d; i++) {
        float4 v = *(const float4*)(h + (size_t)ss[i] * HH + (lane << 2));
        acc.x += v.x; acc.y += v.y; acc.z += v.z; acc.w += v.w;
    }
    *(float4*)(agg + (size_t)node * HH + (lane << 2)) = acc;
}

// weighted cls agg, batched over experts, with batch-prefetch of scalar operands.
// Lanes prefetch up to 32 neighbors' (src, eon, nm) in parallel (MLP=32), then
// the gather loop consumes them via shuffles in ascending-i order -> bit-identical.
template <bool MASKX>
__global__ void k_agg_cls(const float* __restrict__ x, const float* __restrict__ nm,
                          const int* __restrict__ deg, const int* __restrict__ adj_src,
                          const int* __restrict__ adj_eid) {
    int node = blockIdx.x * (blockDim.x >> 5) + (threadIdx.x >> 5);
    if (node >= NN) return;
    int k = blockIdx.y;
    float* a = arena(k);
    const float* h = MASKX ? x : a;
    float* agg = a + 2 * (size_t)NN * HH;
    const float* eon = a + 3 * (size_t)NN * HH;
    int lane = threadIdx.x & 31;
    int d = deg[node]; if (d > CAP) d = CAP;
    const int* ss = adj_src + node * CAP;
    const int* es = adj_eid + node * CAP;
    float4 acc = make_float4(0.f, 0.f, 0.f, 0.f);

    for (int base = 0; base < d; base += 32) {
        int i_l = base + lane;
        int s_l = 0;
        float w_l = 0.f;
        float m_l = 0.f;
        if (i_l < d) {
            s_l = ss[i_l];                       // coalesced
            w_l = eon[es[i_l]];                  // scattered, but MLP=32 batch
            if (MASKX) m_l = nm[(size_t)s_l * KK + k];
        }
        int n_it = d - base; if (n_it > 32) n_it = 32;
        for (int j = 0; j < n_it; j++) {
            float w = __shfl_sync(0xffffffffu, w_l, j);
            if (w == 0.f) continue;              // warp-uniform
            int s = __shfl_sync(0xffffffffu, s_l, j);
            float4 v = *(const float4*)(h + (size_t)s * HH + (lane << 2));
            if (MASKX) {
                float m = __shfl_sync(0xffffffffu, m_l, j);
                v.x *= m; v.y *= m; v.z *= m; v.w *= m;
            }
            acc.x += w * v.x; acc.y += w * v.y; acc.z += w * v.z; acc.w += w * v.w;
        }
    }
    *(float4*)(agg + (size_t)node * HH + (lane << 2)) = acc;
}

// ---------------- pipelined 64x128x128 GEMM core (R13 mapping: row-block per warp) ----------------
__device__ __forceinline__ void gemm_quarters(const float* As, float* Wb0, float* Wb1,
                                              const float* __restrict__ W, int tid,
                                              int r0, int c0, unsigned long long acc[8][2]) {
    load_wq(Wb0, W, tid);
    CP_COMMIT(); CP_WAIT0();
    __syncthreads();
#pragma unroll 1
    for (int q = 0; q < 4; q++) {
        float* cur = (q & 1) ? Wb1 : Wb0;
        if (q < 3) { load_wq((q & 1) ? Wb0 : Wb1, W + (size_t)(q + 1) * 32 * HH, tid); CP_COMMIT(); }
        const float* arow = As + r0 * 132 + q * 32;
#pragma unroll 2
        for (int k = 0; k < 32; k += 4) {
            ulonglong2 b0 = *(const ulonglong2*)(cur + (k + 0) * 132 + c0);
            ulonglong2 b1v = *(const ulonglong2*)(cur + (k + 1) * 132 + c0);
            ulonglong2 b2v = *(const ulonglong2*)(cur + (k + 2) * 132 + c0);
            ulonglong2 b3v = *(const ulonglong2*)(cur + (k + 3) * 132 + c0);
#pragma unroll
            for (int i = 0; i < 8; i++) {
                float4 a4 = *(const float4*)(arow + i * 132 + k);
                unsigned long long ax = dup2(a4.x), ay = dup2(a4.y);
                unsigned long long az = dup2(a4.z), aw = dup2(a4.w);
                ffma2(acc[i][0], ax, b0.x);  ffma2(acc[i][1], ax, b0.y);
                ffma2(acc[i][0], ay, b1v.x); ffma2(acc[i][1], ay, b1v.y);
                ffma2(acc[i][0], az, b2v.x); ffma2(acc[i][1], az, b2v.y);
                ffma2(acc[i][0], aw, b3v.x); ffma2(acc[i][1], aw, b3v.y);
            }
        }
        if (q < 3) CP_WAIT0();
        __syncthreads();
    }
}

// ---------------- fused MLP (agg-in epilogue, 2 GEMMs, pipelined W) ----------------
template <bool MASKX>
__device__ __forceinline__ void mlp_body(float* sm,
    const float* __restrict__ X, const float* __restrict__ nm, int kidx,
    const float* __restrict__ AGG, const float* __restrict__ epsp,
    const float* __restrict__ W1, const float* __restrict__ b1,
    const float* __restrict__ W2, const float* __restrict__ b2,
    float* __restrict__ out, int row0)
{
    float* As  = sm;               // [64][132]
    float* Wb0 = sm + 64 * 132;    // [32][132]
    float* Wb1 = Wb0 + 32 * 132;   // [32][132]
    int tid = threadIdx.x;
    float ep = 1.f + *epsp;

    for (int i = tid; i < 64 * 32; i += 256) {
        int r = i >> 5;
        int cc = (i & 31) << 2;
        int gr = row0 + r;
        float4 v = make_float4(0.f, 0.f, 0.f, 0.f);
        if (gr < NN) {
            v = *(const float4*)(X + (size_t)gr * HH + cc);
            if (MASKX) {
                float m = nm[(size_t)gr * KK + kidx];
                v.x *= m; v.y *= m; v.z *= m; v.w *= m;
            }
            float4 a = *(const float4*)(AGG + (size_t)gr * HH + cc);
            v.x = __fmaf_rn(ep, v.x, a.x); v.y = __fmaf_rn(ep, v.y, a.y);
            v.z = __fmaf_rn(ep, v.z, a.z); v.w = __fmaf_rn(ep, v.w, a.w);
        }
        *(float4*)&As[r * 132 + cc] = v;
    }
    // As made visible by the sync inside gemm_quarters (after W q0 load).

    int r0 = (tid >> 5) * 8;
    int c0 = (tid & 31) * 4;
    unsigned long long acc[8][2];

    // ---- GEMM 1 ----
#pragma unroll
    for (int i = 0; i < 8; i++) { acc[i][0] = 0ull; acc[i][1] = 0ull; }
    gemm_quarters(As, Wb0, Wb1, W1, tid, r0, c0, acc);

    // mid -> As
    {
        float4 bv = *(const float4*)(b1 + c0);
#pragma unroll
        for (int i = 0; i < 8; i++) {
            float x0, x1, x2, x3;
            unpack2(acc[i][0], x0, x1);
            unpack2(acc[i][1], x2, x3);
            x0 += bv.x; x1 += bv.y; x2 += bv.z; x3 += bv.w;
            x0 = fmaxf(x0, 0.f); x1 = fmaxf(x1, 0.f);
            x2 = fmaxf(x2, 0.f); x3 = fmaxf(x3, 0.f);
            *(float4*)&As[(r0 + i) * 132 + c0] = make_float4(x0, x1, x2, x3);
        }
    }

    // ---- GEMM 2 ----
#pragma unroll
    for (int i = 0; i < 8; i++) { acc[i][0] = 0ull; acc[i][1] = 0ull; }
    gemm_quarters(As, Wb0, Wb1, W2, tid, r0, c0, acc);

    {
        float4 bv = *(const float4*)(b2 + c0);
#pragma unroll
        for (int i = 0; i < 8; i++) {
            int gr = row0 + r0 + i;
            if (gr < NN) {
                float x0, x1, x2, x3;
                unpack2(acc[i][0], x0, x1);
                unpack2(acc[i][1], x2, x3);
                x0 += bv.x; x1 += bv.y; x2 += bv.z; x3 += bv.w;
                x0 = fmaxf(x0, 0.f); x1 = fmaxf(x1, 0.f);
                x2 = fmaxf(x2, 0.f); x3 = fmaxf(x3, 0.f);
                *(float4*)(out + (size_t)gr * HH + c0) = make_float4(x0, x1, x2, x3);
            }
        }
    }
}

__global__ void __launch_bounds__(256, 3)
k_mlp_enc(const float* __restrict__ X, const float* __restrict__ AGG,
          const float* __restrict__ epsp,
          const float* __restrict__ W1, const float* __restrict__ b1,
          const float* __restrict__ W2, const float* __restrict__ b2,
          float* __restrict__ out) {
    extern __shared__ float sm[];
    mlp_body<false>(sm, X, nullptr, 0, AGG, epsp, W1, b1, W2, b2, out, blockIdx.x * 64);
}

__global__ void __launch_bounds__(256, 3)
k_mlp_cls(int l, const float* __restrict__ x, const float* __restrict__ nm,
          const float* __restrict__ cls_eps,
          const float* __restrict__ cls_W1, const float* __restrict__ cls_b1,
          const float* __restrict__ cls_W2, const float* __restrict__ cls_b2) {
    extern __shared__ float sm[];
    int k = blockIdx.y;
    int wl = k * 3 + l;
    float* a = arena(k);
    if (l == 0) {
        mlp_body<true>(sm, x, nm, k, a + 2 * (size_t)NN * HH, cls_eps + wl,
                       cls_W1 + (size_t)wl * HH * HH, cls_b1 + wl * HH,
                       cls_W2 + (size_t)wl * HH * HH, cls_b2 + wl * HH,
                       a, blockIdx.x * 64);
    } else {
        mlp_body<false>(sm, a, nullptr, 0, a + 2 * (size_t)NN * HH, cls_eps + wl,
                        cls_W1 + (size_t)wl * HH * HH, cls_b1 + wl * HH,
                        cls_W2 + (size_t)wl * HH * HH, cls_b2 + wl * HH,
                        a, blockIdx.x * 64);
    }
}

// ---------------- mask projection GEMM, batched grid (GB, 2, K), pipelined W ----------------
__global__ void __launch_bounds__(256, 3)
k_gemm_mask(const float* __restrict__ Z, const float* __restrict__ mask_W1) {
    extern __shared__ float sm[];
    float* As  = sm;
    float* Wb0 = sm + 64 * 132;
    float* Wb1 = Wb0 + 32 * 132;
    int tid = threadIdx.x;
    int row0 = blockIdx.x * 64;
    int k = blockIdx.z;
    const float* W = mask_W1 + ((size_t)k * 2 + blockIdx.y) * HH * HH;
    float* out = arena(k) + (1 + blockIdx.y) * (size_t)NN * HH;

    for (int i = tid; i < 64 * 32; i += 256) {
        int r = i >> 5;
        int cc = (i & 31) << 2;
        int gr = row0 + r;
        float4 v = make_float4(0.f, 0.f, 0.f, 0.f);
        if (gr < NN) v = *(const float4*)(Z + (size_t)gr * HH + cc);
        *(float4*)&As[r * 132 + cc] = v;
    }

    int r0 = (tid >> 5) * 8;
    int c0 = (tid & 31) * 4;
    unsigned long long acc[8][2];
#pragma unroll
    for (int i = 0; i < 8; i++) { acc[i][0] = 0ull; acc[i][1] = 0ull; }
    gemm_quarters(As, Wb0, Wb1, W, tid, r0, c0, acc);

#pragma unroll
    for (int i = 0; i < 8; i++) {
        int gr = row0 + r0 + i;
        if (gr < NN) {
            float x0, x1, x2, x3;
            unpack2(acc[i][0], x0, x1);
            unpack2(acc[i][1], x2, x3);
            *(float4*)(out + (size_t)gr * HH + c0) = make_float4(x0, x1, x2, x3);
        }
    }
}

// ---------------- edge mask (warp per edge, batched over experts) ----------------
__global__ void k_edgemask(const int* __restrict__ src, const int* __restrict__ dst,
                           const float* __restrict__ u, const float* __restrict__ mask_b1,
                           const float* __restrict__ mask_w2, const float* __restrict__ mask_b2,
                           float* __restrict__ nm, float* __restrict__ em) {
    int e = blockIdx.x * (blockDim.x >> 5) + (threadIdx.x >> 5);
    if (e >= EE) return;
    int kk = blockIdx.y;
    float* a4 = arena(kk);
    const float* Abuf = a4 + (size_t)NN * HH;
    const float* Bbuf = a4 + 2 * (size_t)NN * HH;
    float* eon = a4 + 3 * (size_t)NN * HH;
    const float* b1 = mask_b1 + kk * HH;
    const float* w2 = mask_w2 + kk * HH;

    int lane = threadIdx.x & 31;
    int s = src[e], d = dst[e];
    float4 a = *(const float4*)(Abuf + (size_t)s * HH + (lane << 2));
    float4 b = *(const float4*)(Bbuf + (size_t)d * HH + (lane << 2));
    float4 bb = *(const float4*)(b1 + (lane << 2));
    float4 wv = *(const float4*)(w2 + (lane << 2));
    float h0 = fmaxf(a.x + b.x + bb.x, 0.f);
    float h1 = fmaxf(a.y + b.y + bb.y, 0.f);
    float h2 = fmaxf(a.z + b.z + bb.z, 0.f);
    float h3 = fmaxf(a.w + b.w + bb.w, 0.f);
    float p = h0 * wv.x + h1 * wv.y + h2 * wv.z + h3 * wv.w;
#pragma unroll
    for (int off = 16; off; off >>= 1) p += __shfl_xor_sync(0xffffffffu, p, off);
    if (lane == 0) {
        float eml = p + mask_b2[kk];
        float uu = u[(size_t)e * KK + kk];
        float g = -logf(-logf(uu + 1e-20f) + 1e-20f);
        float t = (eml + g) / 0.1f;
        float ys = 1.f / (1.f + expf(-t));
        float hard = (ys > 0.5f) ? 1.f : 0.f;
        float eo = (hard + ys) - ys;
        eon[e] = eo;
        em[(size_t)e * KK + kk] = eo;
        if (eo > 0.f) {
            nm[(size_t)s * KK + kk] = 1.f;
            nm[(size_t)d * KK + kk] = 1.f;
        }
    }
}

// ---------------- fused pool + head (+ h_orig plane): grid (BB, KK+1), 128 threads ----------------
__global__ void k_poolhead(const float* __restrict__ Z,
                           const int* __restrict__ cnt, const int* __restrict__ bstart,
                           const float* __restrict__ head_W1, const float* __restrict__ head_b1,
                           const float* __restrict__ head_W2, const float* __restrict__ head_b2,
                           float* __restrict__ out_hstab, float* __restrict__ out_logits,
                           float* __restrict__ out_horig) {
    __shared__ float sh[128], T[128];
    int g = blockIdx.x, kk = blockIdx.y, c = threadIdx.x;
    const float* h = (kk == KK) ? Z : arena(kk);
    int n0 = bstart[g], n = cnt[g];
    float a0 = 0.f, a1 = 0.f, a2 = 0.f, a3 = 0.f;
    int i = 0;
    for (; i + 4 <= n; i += 4) {
        a0 += h[(size_t)(n0 + i + 0) * HH + c];
        a1 += h[(size_t)(n0 + i + 1) * HH + c];
        a2 += h[(size_t)(n0 + i + 2) * HH + c];
        a3 += h[(size_t)(n0 + i + 3) * HH + c];
    }
    float acc = (a0 + a1) + (a2 + a3);
    for (; i < n; i++) acc += h[(size_t)(n0 + i) * HH + c];
    float v = acc / fmaxf((float)n, 1.f);

    if (kk == KK) {
        out_horig[(size_t)g * HH + c] = v;
        return;
    }
    out_hstab[((size_t)g * KK + kk) * HH + c] = v;
    sh[c] = v;
    __syncthreads();

    const float* W1 = head_W1 + (size_t)kk * HH * HH;
    float t = head_b1[kk * HH + c];
#pragma unroll 8
    for (int j = 0; j < 128; j++) t += sh[j] * W1[j * HH + c];
    T[c] = fmaxf(t, 0.f);
    __syncthreads();
    if (c < 2) {
        const float* W2 = head_W2 + (size_t)kk * HH * 2;
        float s = head_b2[kk * 2 + c];
        for (int j = 0; j < 128; j++) s += T[j] * W2[j * 2 + c];
        out_logits[((size_t)g * KK + kk) * 2 + c] = s;
    }
}

// ---------------- launcher ----------------
extern "C" void kernel_launch(void* const* d_in, const int* in_sizes, int n_in,
                              void* d_out, int out_size) {
    const float* x       = (const float*)d_in[0];
    const int*   ei      = (const int*)d_in[1];
    const int*   src     = ei;
    const int*   dst     = ei + EE;
    const int*   batch   = (const int*)d_in[2];
    const float* u       = (const float*)d_in[3];
    const float* enc_W1  = (const float*)d_in[4];
    const float* enc_b1  = (const float*)d_in[5];
    const float* enc_W2  = (const float*)d_in[6];
    const float* enc_b2  = (const float*)d_in[7];
    const float* enc_eps = (const float*)d_in[8];
    const float* cls_W1  = (const float*)d_in[9];
    const float* cls_b1  = (const float*)d_in[10];
    const float* cls_W2  = (const float*)d_in[11];
    const float* cls_b2  = (const float*)d_in[12];
    const float* cls_eps = (const float*)d_in[13];
    const float* mask_W1 = (const float*)d_in[14];
    const float* mask_b1 = (const float*)d_in[15];
    const float* mask_W2 = (const float*)d_in[16];
    const float* mask_b2 = (const float*)d_in[17];
    const float* head_W1 = (const float*)d_in[18];
    const float* head_b1 = (const float*)d_in[19];
    const float* head_W2 = (const float*)d_in[20];
    const float* head_b2 = (const float*)d_in[21];
    float* out = (float*)d_out;

    unsigned char* base = nullptr;
    cudaGetSymbolAddress((void**)&base, g_scratch);
    float* p_Z      = (float*)(base + SC_Z);
    int*   p_deg    = (int*)(base + SC_DEG);
    int*   p_asrc   = (int*)(base + SC_ADJSRC);
    int*   p_aeid   = (int*)(base + SC_ADJEID);
    int*   p_cnt    = (int*)(base + SC_CNT);
    int*   p_bstart = (int*)(base + SC_BSTART);
    float* arena0   = (float*)(base + SC_EXP);

    cudaFuncSetAttribute(k_mlp_enc,   cudaFuncAttributeMaxDynamicSharedMemorySize, SMEM_BYTES);
    cudaFuncSetAttribute(k_mlp_cls,   cudaFuncAttributeMaxDynamicSharedMemorySize, SMEM_BYTES);
    cudaFuncSetAttribute(k_gemm_mask, cudaFuncAttributeMaxDynamicSharedMemorySize, SMEM_BYTES);

    const int GB = (NN + 63) / 64;
    const int AB = (NN + 7) / 8;
    const int EB = (EE + 7) / 8;

    float* t0    = arena0;                        // enc temp h
    float* t_agg = arena0 + 2 * (size_t)NN * HH;  // enc agg temp

    // graph setup
    k_zero_all<<<(NN * KK + 255) / 256, 256>>>(p_deg, out + OFF_NM);
    k_build_adj<<<(EE + 255) / 256, 256>>>(src, dst, p_deg, p_asrc, p_aeid);
    k_sort_adj<<<(NN + 255) / 256, 256>>>(p_deg, p_asrc, p_aeid);

    // enc l0
    k_agg_enc<<<AB, 256>>>(x, t_agg, p_deg, p_asrc);
    k_bounds<<<1, BB>>>(batch, p_cnt, p_bstart);
    k_mlp_enc<<<GB, 256, SMEM_BYTES>>>(x, t_agg, enc_eps + 0, enc_W1, enc_b1,
                                       enc_W2, enc_b2, t0);

    // enc l1 (in-place t0), l2 (-> p_Z)
    k_agg_enc<<<AB, 256>>>(t0, t_agg, p_deg, p_asrc);
    k_mlp_enc<<<GB, 256, SMEM_BYTES>>>(t0, t_agg, enc_eps + 1, enc_W1 + HH * HH, enc_b1 + HH,
                                       enc_W2 + HH * HH, enc_b2 + HH, t0);
    k_agg_enc<<<AB, 256>>>(t0, t_agg, p_deg, p_asrc);
    k_mlp_enc<<<GB, 256, SMEM_BYTES>>>(t0, t_agg, enc_eps + 2, enc_W1 + 2 * HH * HH,
                                       enc_b1 + 2 * HH, enc_W2 + 2 * HH * HH, enc_b2 + 2 * HH, p_Z);

    // mask phase (batched)
    k_gemm_mask<<<dim3(GB, 2, KK), 256, SMEM_BYTES>>>(p_Z, mask_W1);
    k_edgemask<<<dim3(EB, KK), 256>>>(src, dst, u, mask_b1, mask_W2, mask_b2,
                                      out + OFF_NM, out + OFF_EM);

    // cls layers (batched over experts)
    k_agg_cls<true><<<dim3(AB, KK), 256>>>(x, out + OFF_NM, p_deg, p_asrc, p_aeid);
    k_mlp_cls<<<dim3(GB, KK), 256, SMEM_BYTES>>>(0, x, out + OFF_NM, cls_eps,
                                                 cls_W1, cls_b1, cls_W2, cls_b2);
    for (int l = 1; l < 3; l++) {
        k_agg_cls<false><<<dim3(AB, KK), 256>>>(x, out + OFF_NM, p_deg, p_asrc, p_aeid);
        k_mlp_cls<<<dim3(GB, KK), 256, SMEM_BYTES>>>(l, x, out + OFF_NM, cls_eps,
                                                     cls_W1, cls_b1, cls_W2, cls_b2);
    }

    // pools + heads (+ h_orig as extra y-plane)
    k_poolhead<<<dim3(BB, KK + 1), 128>>>(p_Z, p_cnt, p_bstart,
                                          head_W1, head_b1, head_W2, head_b2,
                                          out + OFF_HSTAB, out + OFF_LOGITS, out + OFF_HORIG);
}

// round 16
// speedup vs baseline: 1.0759x; 1.0051x over previous
#include <cuda_runtime.h>
#include <cstddef>
#include <cstdint>

#define NN 20000
#define EE 320000
#define HH 128
#define KK 4
#define BB 64
#define CAP 64

#define OFF_LOGITS 0
#define OFF_HSTAB  512
#define OFF_HORIG  33280
#define OFF_NM     41472
#define OFF_EM     121472

#define NH4 ((size_t)NN * HH * 4)
#define SMEM_BYTES (128 * 132 * 4)

// scratch layout
#define SC_Z       0
#define SC_DEG     (SC_Z + NH4)
#define SC_ADJSRC  (SC_DEG + (size_t)NN * 4)
#define SC_ADJEID  (SC_ADJSRC + (size_t)NN * CAP * 4)
#define SC_CNT     (SC_ADJEID + (size_t)NN * CAP * 4)
#define SC_BSTART  (SC_CNT + (size_t)BB * 4)
#define SC_EPOS    (SC_BSTART + 384)
#define SC_EXP     (SC_EPOS + (size_t)EE * 4)
// per-expert: buf0 (N*H), buf1 (N*H), buf2/agg (N*H), w_adj (N*CAP)
#define EXP_STRIDE_F (3 * (size_t)NN * HH + (size_t)NN * CAP)
#define SC_TOTAL   (SC_EXP + 4 * EXP_STRIDE_F * 4)

__device__ __align__(128) unsigned char g_scratch[SC_TOTAL];

// ---------------- helpers ----------------
__device__ __forceinline__ void ffma2(unsigned long long& d, unsigned long long a, unsigned long long b) {
    asm("fma.rn.f32x2 %0, %1, %2, %0;" : "+l"(d) : "l"(a), "l"(b));
}
__device__ __forceinline__ unsigned long long dup2(float x) {
    unsigned long long r;
    asm("mov.b64 %0, {%1, %1};" : "=l"(r) : "f"(x));
    return r;
}
__device__ __forceinline__ void unpack2(unsigned long long v, float& lo, float& hi) {
    asm("mov.b64 {%0, %1}, %2;" : "=f"(lo), "=f"(hi) : "l"(v));
}
__device__ __forceinline__ float* arena(int k) {
    return (float*)(g_scratch + SC_EXP) + (size_t)k * EXP_STRIDE_F;
}
__device__ __forceinline__ void cp16(void* smem_dst, const void* gmem_src) {
    uint32_t s = (uint32_t)__cvta_generic_to_shared(smem_dst);
    asm volatile("cp.async.cg.shared.global [%0], [%1], 16;" :: "r"(s), "l"(gmem_src));
}
#define CP_COMMIT() asm volatile("cp.async.commit_group;" ::: "memory")
#define CP_WAIT0()  asm volatile("cp.async.wait_group 0;" ::: "memory")

__device__ __forceinline__ void load_wq(float* buf, const float* Wsrc, int tid) {
#pragma unroll
    for (int c = tid; c < 1024; c += 256) {
        int r = c >> 5;
        int col = c & 31;
        cp16(buf + r * 132 + col * 4, Wsrc + (size_t)r * HH + col * 4);
    }
}

// ---------------- setup ----------------
__global__ void k_zero_all(int* deg, float* nm) {
    int i = blockIdx.x * blockDim.x + threadIdx.x;
    if (i < NN) deg[i] = 0;
    if (i < NN * KK) nm[i] = 0.f;
}

__global__ void k_build_adj(const int* __restrict__ src, const int* __restrict__ dst,
                            int* deg, int* adj_src, int* adj_eid, int* epos) {
    int e = blockIdx.x * blockDim.x + threadIdx.x;
    if (e >= EE) return;
    epos[e] = -1;
    int d = dst[e];
    int slot = atomicAdd(&deg[d], 1);
    if (slot < CAP) {
        adj_src[d * CAP + slot] = src[e];
        adj_eid[d * CAP + slot] = e;
    }
}

// sort by edge id, then record inverse map epos[edge] = node*CAP + slot (post-sort)
__global__ void k_sort_adj(const int* __restrict__ deg, int* adj_src, int* adj_eid, int* epos) {
    int n = blockIdx.x * blockDim.x + threadIdx.x;
    if (n >= NN) return;
    int d = deg[n]; if (d > CAP) d = CAP;
    int* es = adj_eid + n * CAP;
    int* ss = adj_src + n * CAP;
    for (int i = 1; i < d; i++) {
        int ke = es[i], ks = ss[i];
        int j = i - 1;
        while (j >= 0 && es[j] > ke) { es[j + 1] = es[j]; ss[j + 1] = ss[j]; j--; }
        es[j + 1] = ke; ss[j + 1] = ks;
    }
    for (int i = 0; i < d; i++) epos[es[i]] = n * CAP + i;
}

// batch is sorted: cnt/bstart via binary search
__global__ void k_bounds(const int* __restrict__ batch, int* cnt, int* bstart) {
    int g = threadIdx.x;
    if (g >= BB) return;
    int lo = 0, hi = NN;
    while (lo < hi) { int mid = (lo + hi) >> 1; if (batch[mid] < g) lo = mid + 1; else hi = mid; }
    int lo2 = lo, hi2 = NN;
    while (lo2 < hi2) { int mid = (lo2 + hi2) >> 1; if (batch[mid] < g + 1) lo2 = mid + 1; else hi2 = mid; }
    bstart[g] = lo;
    cnt[g] = lo2 - lo;
}

// ---------------- aggregation ----------------
__global__ void k_agg_enc(const float* __restrict__ h, float* __restrict__ agg,
                          const int* __restrict__ deg, const int* __restrict__ adj_src) {
    int node = blockIdx.x * (blockDim.x >> 5) + (threadIdx.x >> 5);
    if (node >= NN) return;
    int lane = threadIdx.x & 31;
    int d = deg[node]; if (d > CAP) d = CAP;
    const int* ss = adj_src + node * CAP;
    float4 acc = make_float4(0.f, 0.f, 0.f, 0.f);
    for (int i = 0; i < d; i++) {
        float4 v = *(const float4*)(h + (size_t)ss[i] * HH + (lane << 2));
        acc.x += v.x; acc.y += v.y; acc.z += v.z; acc.w += v.w;
    }
    *(float4*)(agg + (size_t)node * HH + (lane << 2)) = acc;
}

// weighted cls agg: weights read COALESCED from adjacency-ordered w_adj.
// Lanes batch-prefetch (src, w, nm) with MLP=32, consume via shuffles in
// ascending-i order -> bit-identical accumulation.
template <bool MASKX>
__global__ void k_agg_cls(const float* __restrict__ x, const float* __restrict__ nm,
                          const int* __restrict__ deg, const int* __restrict__ adj_src) {
    int node = blockIdx.x * (blockDim.x >> 5) + (threadIdx.x >> 5);
    if (node >= NN) return;
    int k = blockIdx.y;
    float* a = arena(k);
    const float* h = MASKX ? x : a;
    float* agg = a + 2 * (size_t)NN * HH;
    const float* wadj = a + 3 * (size_t)NN * HH;
    int lane = threadIdx.x & 31;
    int d = deg[node]; if (d > CAP) d = CAP;
    const int* ss = adj_src + node * CAP;
    const float* ws = wadj + node * CAP;
    float4 acc = make_float4(0.f, 0.f, 0.f, 0.f);

    for (int base = 0; base < d; base += 32) {
        int i_l = base + lane;
        int s_l = 0;
        float w_l = 0.f;
        float m_l = 0.f;
        if (i_l < d) {
            s_l = ss[i_l];      // coalesced
            w_l = ws[i_l];      // coalesced
            if (MASKX) m_l = nm[(size_t)s_l * KK + k];
        }
        int n_it = d - base; if (n_it > 32) n_it = 32;
        for (int j = 0; j < n_it; j++) {
            float w = __shfl_sync(0xffffffffu, w_l, j);
            if (w == 0.f) continue;
            int s = __shfl_sync(0xffffffffu, s_l, j);
            float4 v = *(const float4*)(h + (size_t)s * HH + (lane << 2));
            if (MASKX) {
                float m = __shfl_sync(0xffffffffu, m_l, j);
                v.x *= m; v.y *= m; v.z *= m; v.w *= m;
            }
            acc.x += w * v.x; acc.y += w * v.y; acc.z += w * v.z; acc.w += w * v.w;
        }
    }
    *(float4*)(agg + (size_t)node * HH + (lane << 2)) = acc;
}

// ---------------- pipelined 64x128x128 GEMM core ----------------
__device__ __forceinline__ void gemm_quarters(const float* As, float* Wb0, float* Wb1,
                                              const float* __restrict__ W, int tid,
                                              int r0, int c0, unsigned long long acc[8][2]) {
    load_wq(Wb0, W, tid);
    CP_COMMIT(); CP_WAIT0();
    __syncthreads();
#pragma unroll 1
    for (int q = 0; q < 4; q++) {
        float* cur = (q & 1) ? Wb1 : Wb0;
        if (q < 3) { load_wq((q & 1) ? Wb0 : Wb1, W + (size_t)(q + 1) * 32 * HH, tid); CP_COMMIT(); }
        const float* arow = As + r0 * 132 + q * 32;
#pragma unroll 2
        for (int k = 0; k < 32; k += 4) {
            ulonglong2 b0 = *(const ulonglong2*)(cur + (k + 0) * 132 + c0);
            ulonglong2 b1v = *(const ulonglong2*)(cur + (k + 1) * 132 + c0);
            ulonglong2 b2v = *(const ulonglong2*)(cur + (k + 2) * 132 + c0);
            ulonglong2 b3v = *(const ulonglong2*)(cur + (k + 3) * 132 + c0);
#pragma unroll
            for (int i = 0; i < 8; i++) {
                float4 a4 = *(const float4*)(arow + i * 132 + k);
                unsigned long long ax = dup2(a4.x), ay = dup2(a4.y);
                unsigned long long az = dup2(a4.z), aw = dup2(a4.w);
                ffma2(acc[i][0], ax, b0.x);  ffma2(acc[i][1], ax, b0.y);
                ffma2(acc[i][0], ay, b1v.x); ffma2(acc[i][1], ay, b1v.y);
                ffma2(acc[i][0], az, b2v.x); ffma2(acc[i][1], az, b2v.y);
                ffma2(acc[i][0], aw, b3v.x); ffma2(acc[i][1], aw, b3v.y);
            }
        }
        if (q < 3) CP_WAIT0();
        __syncthreads();
    }
}

// ---------------- fused MLP ----------------
template <bool MASKX>
__device__ __forceinline__ void mlp_body(float* sm,
    const float* __restrict__ X, const float* __restrict__ nm, int kidx,
    const float* __restrict__ AGG, const float* __restrict__ epsp,
    const float* __restrict__ W1, const float* __restrict__ b1,
    const float* __restrict__ W2, const float* __restrict__ b2,
    float* __restrict__ out, int row0)
{
    float* As  = sm;
    float* Wb0 = sm + 64 * 132;
    float* Wb1 = Wb0 + 32 * 132;
    int tid = threadIdx.x;
    float ep = 1.f + *epsp;

    for (int i = tid; i < 64 * 32; i += 256) {
        int r = i >> 5;
        int cc = (i & 31) << 2;
        int gr = row0 + r;
        float4 v = make_float4(0.f, 0.f, 0.f, 0.f);
        if (gr < NN) {
            v = *(const float4*)(X + (size_t)gr * HH + cc);
            if (MASKX) {
                float m = nm[(size_t)gr * KK + kidx];
                v.x *= m; v.y *= m; v.z *= m; v.w *= m;
            }
            float4 a = *(const float4*)(AGG + (size_t)gr * HH + cc);
            v.x = __fmaf_rn(ep, v.x, a.x); v.y = __fmaf_rn(ep, v.y, a.y);
            v.z = __fmaf_rn(ep, v.z, a.z); v.w = __fmaf_rn(ep, v.w, a.w);
        }
        *(float4*)&As[r * 132 + cc] = v;
    }

    int r0 = (tid >> 5) * 8;
    int c0 = (tid & 31) * 4;
    unsigned long long acc[8][2];

#pragma unroll
    for (int i = 0; i < 8; i++) { acc[i][0] = 0ull; acc[i][1] = 0ull; }
    gemm_quarters(As, Wb0, Wb1, W1, tid, r0, c0, acc);

    {
        float4 bv = *(const float4*)(b1 + c0);
#pragma unroll
        for (int i = 0; i < 8; i++) {
            float x0, x1, x2, x3;
            unpack2(acc[i][0], x0, x1);
            unpack2(acc[i][1], x2, x3);
            x0 += bv.x; x1 += bv.y; x2 += bv.z; x3 += bv.w;
            x0 = fmaxf(x0, 0.f); x1 = fmaxf(x1, 0.f);
            x2 = fmaxf(x2, 0.f); x3 = fmaxf(x3, 0.f);
            *(float4*)&As[(r0 + i) * 132 + c0] = make_float4(x0, x1, x2, x3);
        }
    }

#pragma unroll
    for (int i = 0; i < 8; i++) { acc[i][0] = 0ull; acc[i][1] = 0ull; }
    gemm_quarters(As, Wb0, Wb1, W2, tid, r0, c0, acc);

    {
        float4 bv = *(const float4*)(b2 + c0);
#pragma unroll
        for (int i = 0; i < 8; i++) {
            int gr = row0 + r0 + i;
            if (gr < NN) {
                float x0, x1, x2, x3;
                unpack2(acc[i][0], x0, x1);
                unpack2(acc[i][1], x2, x3);
                x0 += bv.x; x1 += bv.y; x2 += bv.z; x3 += bv.w;
                x0 = fmaxf(x0, 0.f); x1 = fmaxf(x1, 0.f);
                x2 = fmaxf(x2, 0.f); x3 = fmaxf(x3, 0.f);
                *(float4*)(out + (size_t)gr * HH + c0) = make_float4(x0, x1, x2, x3);
            }
        }
    }
}

__global__ void __launch_bounds__(256, 3)
k_mlp_enc(const float* __restrict__ X, const float* __restrict__ AGG,
          const float* __restrict__ epsp,
          const float* __restrict__ W1, const float* __restrict__ b1,
          const float* __restrict__ W2, const float* __restrict__ b2,
          float* __restrict__ out) {
    extern __shared__ float sm[];
    mlp_body<false>(sm, X, nullptr, 0, AGG, epsp, W1, b1, W2, b2, out, blockIdx.x * 64);
}

__global__ void __launch_bounds__(256, 3)
k_mlp_cls(int l, const float* __restrict__ x, const float* __restrict__ nm,
          const float* __restrict__ cls_eps,
          const float* __restrict__ cls_W1, const float* __restrict__ cls_b1,
          const float* __restrict__ cls_W2, const float* __restrict__ cls_b2) {
    extern __shared__ float sm[];
    int k = blockIdx.y;
    int wl = k * 3 + l;
    float* a = arena(k);
    if (l == 0) {
        mlp_body<true>(sm, x, nm, k, a + 2 * (size_t)NN * HH, cls_eps + wl,
                       cls_W1 + (size_t)wl * HH * HH, cls_b1 + wl * HH,
                       cls_W2 + (size_t)wl * HH * HH, cls_b2 + wl * HH,
                       a, blockIdx.x * 64);
    } else {
        mlp_body<false>(sm, a, nullptr, 0, a + 2 * (size_t)NN * HH, cls_eps + wl,
                        cls_W1 + (size_t)wl * HH * HH, cls_b1 + wl * HH,
                        cls_W2 + (size_t)wl * HH * HH, cls_b2 + wl * HH,
                        a, blockIdx.x * 64);
    }
}

// ---------------- mask projection GEMM, batched grid (GB, 2, K) ----------------
__global__ void __launch_bounds__(256, 3)
k_gemm_mask(const float* __restrict__ Z, const float* __restrict__ mask_W1) {
    extern __shared__ float sm[];
    float* As  = sm;
    float* Wb0 = sm + 64 * 132;
    float* Wb1 = Wb0 + 32 * 132;
    int tid = threadIdx.x;
    int row0 = blockIdx.x * 64;
    int k = blockIdx.z;
    const float* W = mask_W1 + ((size_t)k * 2 + blockIdx.y) * HH * HH;
    float* out = arena(k) + (size_t)blockIdx.y * NN * HH;   // buf0 / buf1 (A / B proj)

    for (int i = tid; i < 64 * 32; i += 256) {
        int r = i >> 5;
        int cc = (i & 31) << 2;
        int gr = row0 + r;
        float4 v = make_float4(0.f, 0.f, 0.f, 0.f);
        if (gr < NN) v = *(const float4*)(Z + (size_t)gr * HH + cc);
        *(float4*)&As[r * 132 + cc] = v;
    }

    int r0 = (tid >> 5) * 8;
    int c0 = (tid & 31) * 4;
    unsigned long long acc[8][2];
#pragma unroll
    for (int i = 0; i < 8; i++) { acc[i][0] = 0ull; acc[i][1] = 0ull; }
    gemm_quarters(As, Wb0, Wb1, W, tid, r0, c0, acc);

#pragma unroll
    for (int i = 0; i < 8; i++) {
        int gr = row0 + r0 + i;
        if (gr < NN) {
            float x0, x1, x2, x3;
            unpack2(acc[i][0], x0, x1);
            unpack2(acc[i][1], x2, x3);
            *(float4*)(out + (size_t)gr * HH + c0) = make_float4(x0, x1, x2, x3);
        }
    }
}

// ---------------- edge mask (warp per edge, batched over experts) ----------------
// A-proj in buf0, B-proj in buf1; writes weight into adjacency-ordered w_adj via epos.
__global__ void k_edgemask(const int* __restrict__ src, const int* __restrict__ dst,
                           const int* __restrict__ epos,
                           const float* __restrict__ u, const float* __restrict__ mask_b1,
                           const float* __restrict__ mask_w2, const float* __restrict__ mask_b2,
                           float* __restrict__ nm, float* __restrict__ em) {
    int e = blockIdx.x * (blockDim.x >> 5) + (threadIdx.x >> 5);
    if (e >= EE) return;
    int kk = blockIdx.y;
    float* a4 = arena(kk);
    const float* Abuf = a4;
    const float* Bbuf = a4 + (size_t)NN * HH;
    float* wadj = a4 + 3 * (size_t)NN * HH;
    const float* b1 = mask_b1 + kk * HH;
    const float* w2 = mask_w2 + kk * HH;

    int lane = threadIdx.x & 31;
    int s = src[e], d = dst[e];
    float4 a = *(const float4*)(Abuf + (size_t)s * HH + (lane << 2));
    float4 b = *(const float4*)(Bbuf + (size_t)d * HH + (lane << 2));
    float4 bb = *(const float4*)(b1 + (lane << 2));
    float4 wv = *(const float4*)(w2 + (lane << 2));
    float h0 = fmaxf(a.x + b.x + bb.x, 0.f);
    float h1 = fmaxf(a.y + b.y + bb.y, 0.f);
    float h2 = fmaxf(a.z + b.z + bb.z, 0.f);
    float h3 = fmaxf(a.w + b.w + bb.w, 0.f);
    float p = h0 * wv.x + h1 * wv.y + h2 * wv.z + h3 * wv.w;
#pragma unroll
    for (int off = 16; off; off >>= 1) p += __shfl_xor_sync(0xffffffffu, p, off);
    if (lane == 0) {
        float eml = p + mask_b2[kk];
        float uu = u[(size_t)e * KK + kk];
        float g = -logf(-logf(uu + 1e-20f) + 1e-20f);
        float t = (eml + g) / 0.1f;
        float ys = 1.f / (1.f + expf(-t));
        float hard = (ys > 0.5f) ? 1.f : 0.f;
        float eo = (hard + ys) - ys;
        em[(size_t)e * KK + kk] = eo;
        int p2 = epos[e];
        if (p2 >= 0) wadj[p2] = eo;
        if (eo > 0.f) {
            nm[(size_t)s * KK + kk] = 1.f;
            nm[(size_t)d * KK + kk] = 1.f;
        }
    }
}

// ---------------- fused pool + head (+ h_orig plane) ----------------
__global__ void k_poolhead(const float* __restrict__ Z,
                           const int* __restrict__ cnt, const int* __restrict__ bstart,
                           const float* __restrict__ head_W1, const float* __restrict__ head_b1,
                           const float* __restrict__ head_W2, const float* __restrict__ head_b2,
                           float* __restrict__ out_hstab, float* __restrict__ out_logits,
                           float* __restrict__ out_horig) {
    __shared__ float sh[128], T[128];
    int g = blockIdx.x, kk = blockIdx.y, c = threadIdx.x;
    const float* h = (kk == KK) ? Z : arena(kk);
    int n0 = bstart[g], n = cnt[g];
    float a0 = 0.f, a1 = 0.f, a2 = 0.f, a3 = 0.f;
    int i = 0;
    for (; i + 4 <= n; i += 4) {
        a0 += h[(size_t)(n0 + i + 0) * HH + c];
        a1 += h[(size_t)(n0 + i + 1) * HH + c];
        a2 += h[(size_t)(n0 + i + 2) * HH + c];
        a3 += h[(size_t)(n0 + i + 3) * HH + c];
    }
    float acc = (a0 + a1) + (a2 + a3);
    for (; i < n; i++) acc += h[(size_t)(n0 + i) * HH + c];
    float v = acc / fmaxf((float)n, 1.f);

    if (kk == KK) {
        out_horig[(size_t)g * HH + c] = v;
        return;
    }
    out_hstab[((size_t)g * KK + kk) * HH + c] = v;
    sh[c] = v;
    __syncthreads();

    const float* W1 = head_W1 + (size_t)kk * HH * HH;
    float t = head_b1[kk * HH + c];
#pragma unroll 8
    for (int j = 0; j < 128; j++) t += sh[j] * W1[j * HH + c];
    T[c] = fmaxf(t, 0.f);
    __syncthreads();
    if (c < 2) {
        const float* W2 = head_W2 + (size_t)kk * HH * 2;
        float s = head_b2[kk * 2 + c];
        for (int j = 0; j < 128; j++) s += T[j] * W2[j * 2 + c];
        out_logits[((size_t)g * KK + kk) * 2 + c] = s;
    }
}

// ---------------- launcher ----------------
extern "C" void kernel_launch(void* const* d_in, const int* in_sizes, int n_in,
                              void* d_out, int out_size) {
    const float* x       = (const float*)d_in[0];
    const int*   ei      = (const int*)d_in[1];
    const int*   src     = ei;
    const int*   dst     = ei + EE;
    const int*   batch   = (const int*)d_in[2];
    const float* u       = (const float*)d_in[3];
    const float* enc_W1  = (const float*)d_in[4];
    const float* enc_b1  = (const float*)d_in[5];
    const float* enc_W2  = (const float*)d_in[6];
    const float* enc_b2  = (const float*)d_in[7];
    const float* enc_eps = (const float*)d_in[8];
    const float* cls_W1  = (const float*)d_in[9];
    const float* cls_b1  = (const float*)d_in[10];
    const float* cls_W2  = (const float*)d_in[11];
    const float* cls_b2  = (const float*)d_in[12];
    const float* cls_eps = (const float*)d_in[13];
    const float* mask_W1 = (const float*)d_in[14];
    const float* mask_b1 = (const float*)d_in[15];
    const float* mask_W2 = (const float*)d_in[16];
    const float* mask_b2 = (const float*)d_in[17];
    const float* head_W1 = (const float*)d_in[18];
    const float* head_b1 = (const float*)d_in[19];
    const float* head_W2 = (const float*)d_in[20];
    const float* head_b2 = (const float*)d_in[21];
    float* out = (float*)d_out;

    unsigned char* base = nullptr;
    cudaGetSymbolAddress((void**)&base, g_scratch);
    float* p_Z      = (float*)(base + SC_Z);
    int*   p_deg    = (int*)(base + SC_DEG);
    int*   p_asrc   = (int*)(base + SC_ADJSRC);
    int*   p_aeid   = (int*)(base + SC_ADJEID);
    int*   p_cnt    = (int*)(base + SC_CNT);
    int*   p_bstart = (int*)(base + SC_BSTART);
    int*   p_epos   = (int*)(base + SC_EPOS);
    float* arena0   = (float*)(base + SC_EXP);

    cudaFuncSetAttribute(k_mlp_enc,   cudaFuncAttributeMaxDynamicSharedMemorySize, SMEM_BYTES);
    cudaFuncSetAttribute(k_mlp_cls,   cudaFuncAttributeMaxDynamicSharedMemorySize, SMEM_BYTES);
    cudaFuncSetAttribute(k_gemm_mask, cudaFuncAttributeMaxDynamicSharedMemorySize, SMEM_BYTES);

    const int GB = (NN + 63) / 64;
    const int AB = (NN + 7) / 8;
    const int EB = (EE + 7) / 8;

    float* t0    = arena0;                        // enc temp h
    float* t_agg = arena0 + 2 * (size_t)NN * HH;  // enc agg temp

    // graph setup
    k_zero_all<<<(NN * KK + 255) / 256, 256>>>(p_deg, out + OFF_NM);
    k_build_adj<<<(EE + 255) / 256, 256>>>(src, dst, p_deg, p_asrc, p_aeid, p_epos);
    k_sort_adj<<<(NN + 255) / 256, 256>>>(p_deg, p_asrc, p_aeid, p_epos);

    // enc l0
    k_agg_enc<<<AB, 256>>>(x, t_agg, p_deg, p_asrc);
    k_bounds<<<1, BB>>>(batch, p_cnt, p_bstart);
    k_mlp_enc<<<GB, 256, SMEM_BYTES>>>(x, t_agg, enc_eps + 0, enc_W1, enc_b1,
                                       enc_W2, enc_b2, t0);

    // enc l1 (in-place t0), l2 (-> p_Z)
    k_agg_enc<<<AB, 256>>>(t0, t_agg, p_deg, p_asrc);
    k_mlp_enc<<<GB, 256, SMEM_BYTES>>>(t0, t_agg, enc_eps + 1, enc_W1 + HH * HH, enc_b1 + HH,
                                       enc_W2 + HH * HH, enc_b2 + HH, t0);
    k_agg_enc<<<AB, 256>>>(t0, t_agg, p_deg, p_asrc);
    k_mlp_enc<<<GB, 256, SMEM_BYTES>>>(t0, t_agg, enc_eps + 2, enc_W1 + 2 * HH * HH,
                                       enc_b1 + 2 * HH, enc_W2 + 2 * HH * HH, enc_b2 + 2 * HH, p_Z);

    // mask phase: A-proj -> buf0, B-proj -> buf1; edgemask writes w_adj (adjacency order)
    k_gemm_mask<<<dim3(GB, 2, KK), 256, SMEM_BYTES>>>(p_Z, mask_W1);
    k_edgemask<<<dim3(EB, KK), 256>>>(src, dst, p_epos, u, mask_b1, mask_W2, mask_b2,
                                      out + OFF_NM, out + OFF_EM);

    // cls layers (batched over experts). l0 reads x*nm, writes buf0 (overwrites A-proj — consumed).
    k_agg_cls<true><<<dim3(AB, KK), 256>>>(x, out + OFF_NM, p_deg, p_asrc);
    k_mlp_cls<<<dim3(GB, KK), 256, SMEM_BYTES>>>(0, x, out + OFF_NM, cls_eps,
                                                 cls_W1, cls_b1, cls_W2, cls_b2);
    for (int l = 1; l < 3; l++) {
        k_agg_cls<false><<<dim3(AB, KK), 256>>>(x, out + OFF_NM, p_deg, p_asrc);
        k_mlp_cls<<<dim3(GB, KK), 256, SMEM_BYTES>>>(l, x, out + OFF_NM, cls_eps,
                                                     cls_W1, cls_b1, cls_W2, cls_b2);
    }

    // pools + heads (+ h_orig as extra y-plane)
    k_poolhead<<<dim3(BB, KK + 1), 128>>>(p_Z, p_cnt, p_bstart,
                                          head_W1, head_b1, head_W2, head_b2,
                                          out + OFF_HSTAB, out + OFF_LOGITS, out + OFF_HORIG);
}